// round 13
// baseline (speedup 1.0000x reference)
#include <cuda_runtime.h>
#include <cuda_fp16.h>
#include <cstdint>

typedef unsigned int u32;

// ---------------- problem constants ----------------
#define BB 64
#define NN 2048
#define TW 136716
#define TP 32

// ---------------- smem layout (bytes) ----------------
#define SM_A   0          // A fp16 frag-major: [2 m16][16 k16][32 lid][16B] = 16384
#define SM_B   16384      // 2 bufs x 16384 (1 kc each)
#define SM_PAR 49152
// float offsets inside PAR
#define PF_FILMI 0        // [256 cols][8]: bi, wsc/2, bsc/2, wsh, wt0, wt1, w30, w31
                          // (layer0: [0..1023] film0 [col][4]; [1024..2047] W0I [col][4])
#define PF_ROWP  2048     // [32][4]: cc, yp0, yp1, 0
#define PF_YS    2176     // [64]
#define PF_W3T   2240     // [16]
#define PF_RED   2256     // [64]
#define PAR_FLOATS 2320
#define SMEM_TOTAL (49152 + PAR_FLOATS*4)   // 58432

// precomputed fp16 weights, frag-major: [b][l][kc 8][4096 u32] = 16 MB used
__device__ uint4 g_wbf[2097152];

// ---------------- helpers ----------------
__device__ __forceinline__ u32 smem_u32(const void* p) {
    u32 a; asm("{ .reg .u64 t; cvta.to.shared.u64 t, %1; cvt.u32.u64 %0, t; }" : "=r"(a) : "l"(p));
    return a;
}
__device__ __forceinline__ u32 pack_h2(float a, float b) {
    __half2 t = __floats2half2_rn(a, b);
    return *reinterpret_cast<u32*>(&t);
}
__device__ __forceinline__ void lds128(u32& r0, u32& r1, u32& r2, u32& r3, u32 addr) {
    asm volatile("ld.shared.v4.u32 {%0,%1,%2,%3}, [%4];"
                 : "=r"(r0), "=r"(r1), "=r"(r2), "=r"(r3) : "r"(addr));
}
__device__ __forceinline__ void mmaf16(float& c0, float& c1, float& c2, float& c3,
                                       u32 a0, u32 a1, u32 a2, u32 a3,
                                       u32 b0, u32 b1) {
    asm volatile("mma.sync.aligned.m16n8k16.row.col.f32.f16.f16.f32 "
                 "{%0,%1,%2,%3}, {%4,%5,%6,%7}, {%8,%9}, {%0,%1,%2,%3};"
                 : "+f"(c0), "+f"(c1), "+f"(c2), "+f"(c3)
                 : "r"(a0), "r"(a1), "r"(a2), "r"(a3), "r"(b0), "r"(b1));
}
__device__ __forceinline__ void cpasync16(u32 dst, const void* src) {
    asm volatile("cp.async.cg.shared.global [%0], [%1], 16;" :: "r"(dst), "l"(src));
}
#define CP_COMMIT() asm volatile("cp.async.commit_group;" ::: "memory")
#define CP_WAIT0()  asm volatile("cp.async.wait_group 0;" ::: "memory")

__device__ __forceinline__ float ex2f(float x){ float r; asm("ex2.approx.ftz.f32 %0, %1;" : "=f"(r) : "f"(x)); return r; }
__device__ __forceinline__ float lg2f(float x){ float r; asm("lg2.approx.ftz.f32 %0, %1;" : "=f"(r) : "f"(x)); return r; }
__device__ __forceinline__ float tanhf_fast(float x){ float r; asm("tanh.approx.f32 %0, %1;" : "=f"(r) : "f"(x)); return r; }
__device__ __forceinline__ float sigmoid_ht(float halfarg) {
    return fmaf(tanhf_fast(halfarg), 0.5f, 0.5f);
}
__device__ __forceinline__ float softplusf_fast(float x) {
    float e = ex2f(-1.4426950408889634f * fabsf(x));
    return fmaxf(x, 0.0f) + 0.6931471805599453f * lg2f(1.0f + e);
}

// ---------------- prep: f32 W -> fp16 frag-major image ----------------
__global__ __launch_bounds__(256)
void prep_weights_kernel(const float* __restrict__ tnw)
{
    __shared__ float s[32][257];
    int bl = blockIdx.x;           // 0..127
    int l = bl & 1, b = bl >> 1;
    const float* wl = tnw + (size_t)b * TW + (l == 0 ? 2048 : 69120);
    int t = threadIdx.x;
    u32* gh = (u32*)g_wbf;

    for (int kc = 0; kc < 8; ++kc) {
        __syncthreads();
        #pragma unroll
        for (int j = 0; j < 32; ++j) {
            int idx = t + j * 256;               // 8192 floats
            int r = idx >> 8, c = idx & 255;
            s[r][c] = wl[(size_t)(kc * 32 + r) * 256 + c];
        }
        __syncthreads();
        size_t base0 = ((size_t)(b * 2 + l) * 8 + kc) * 4096;
        #pragma unroll
        for (int j = 0; j < 16; ++j) {
            int idx = t + j * 256;               // 0..4095
            int reg = idx & 3;
            int lid = (idx >> 2) & 31;
            int n16 = (idx >> 7) & 15;
            int ks  = idx >> 11;
            int koff = ks * 16 + 2 * (lid & 3) + 8 * (reg & 1);
            int n = n16 * 16 + (lid >> 2) + 8 * (reg >> 1);
            gh[base0 + idx] = pack_h2(s[koff][n], s[koff + 1][n]);
        }
    }
}

// ---------------- main kernel: 256 threads, 8 warps (32x32 warp tiles), 3 CTAs/SM ----------------
__global__ __launch_bounds__(256, 3)
void ode_hypernet_mma_kernel(const float* __restrict__ ctx_g,
                             const float* __restrict__ y_g,
                             const float* __restrict__ yp_g,
                             const float* __restrict__ tnw_g,
                             float* __restrict__ out_g)
{
    extern __shared__ char smc[];
    float* par = (float*)(smc + SM_PAR);
    const u32 smb = smem_u32(smc);

    const int tid = threadIdx.x;
    const int lid = tid & 31;
    const int wid = tid >> 5;        // = wn, 8 warps x 32 cols
    const int b  = blockIdx.y;
    const int p0 = blockIdx.x * TP;
    const float* w = tnw_g + (size_t)b * TW;
    const char* gw = (const char*)g_wbf;

    // item stream: g 0..15 -> layer (g>>3), kc (g&7), buf (g&1); 16KB per item
    auto load_chunk_g = [&](int g) {
        size_t src = ((size_t)(b * 2 + (g >> 3)) * 8 + (size_t)(g & 7)) * 16384;
        u32 dbase = smb + SM_B + (u32)(g & 1) * 16384;
        #pragma unroll
        for (int i = 0; i < 4; ++i) {
            u32 off = (u32)(tid + i * 256) * 16;
            cpasync16(dbase + off, gw + src + off);
        }
        CP_COMMIT();
    };

    // ---- initial loads ----
    if (tid < 32) {
        size_t base = ((size_t)b * NN + p0 + tid) * 2;
        float4 rp = make_float4(ctx_g[(size_t)b * NN + p0 + tid],
                                yp_g[base + 0], yp_g[base + 1], 0.0f);
        *(float4*)&par[PF_ROWP + tid * 4] = rp;
    }
    if (tid < 64) par[PF_YS + tid] = y_g[((size_t)b * NN + p0) * 2 + tid];
    {
        // film0 [col][4] (wsc,bsc pre-halved) and W0I [col][4]
        float4 f0 = make_float4(w[1024 + tid], w[1280 + tid] * 0.5f,
                                w[1536 + tid] * 0.5f, w[1792 + tid]);
        float4 w0 = make_float4(w[tid], w[256 + tid], w[512 + tid], w[768 + tid]);
        *(float4*)&par[PF_FILMI + tid * 4] = f0;
        *(float4*)&par[PF_FILMI + 1024 + tid * 4] = w0;
    }
    if (tid < 16)
        par[PF_W3T + tid] = (tid < 4) ? w[136192 + 512 + tid]
                          : (tid < 12 ? w[136708 + tid - 4] : 0.0f);

    load_chunk_g(0);
    __syncthreads();

    // ---- layer 0 (SIMT): 4 -> 256, FiLM + softplus, write A fp16 frag-major ----
    {
        int p = tid & 31;
        int h2 = tid >> 5;           // 0..7, 32 channels each
        float4 rp = *(float4*)&par[PF_ROWP + p * 4];
        float cc = rp.x, q0 = rp.y, q1 = rp.z;
        float y0 = par[PF_YS + 2 * p], y1 = par[PF_YS + 2 * p + 1];
        int m16 = p >> 4;
        int plid4 = (p & 7) * 4;
        int preg = (p >> 3) & 1;
        #pragma unroll 4
        for (int j = 0; j < 16; ++j) {
            int ch = h2 * 32 + 2 * j;
            float4 wa = *(float4*)&par[PF_FILMI + 1024 + ch * 4];
            float4 wb = *(float4*)&par[PF_FILMI + 1024 + (ch + 1) * 4];
            float4 f0 = *(float4*)&par[PF_FILMI + ch * 4];
            float4 f1 = *(float4*)&par[PF_FILMI + (ch + 1) * 4];
            float v0 = y0 * wa.x + y1 * wa.y + q0 * wa.z + q1 * wa.w + f0.x;
            float v1 = y0 * wb.x + y1 * wb.y + q0 * wb.z + q1 * wb.w + f1.x;
            float s0 = sigmoid_ht(cc * f0.y + f0.z);
            float s1 = sigmoid_ht(cc * f1.y + f1.z);
            v0 = s0 * v0 + cc * f0.w;
            v1 = s1 * v1 + cc * f1.w;
            v0 = softplusf_fast(v0);
            v1 = softplusf_fast(v1);
            int k16 = ch >> 4;
            int flid = plid4 + (j & 3);
            int reg  = preg + 2 * ((j >> 2) & 1);
            u32 off = (u32)((m16 * 16 + k16) * 32 + flid) * 16 + (u32)reg * 4;
            *(u32*)(smc + SM_A + off) = pack_h2(v0, v1);
        }
    }
    CP_WAIT0();
    __syncthreads();

    float ps0[4], ps1[4];            // layer-3 partials (mi x rh)

    #pragma unroll 1
    for (int l = 1; l <= 2; ++l) {
        const float* wl = w + ((l == 1) ? 2048 : 69120);
        const float* fp = wl + 66048;
        {
            // FILMI [col][8]: bi, wsc/2, bsc/2, wsh, wt0, wt1, w30, w31
            float4 pa = make_float4(fp[tid], fp[256 + tid] * 0.5f,
                                    fp[512 + tid] * 0.5f, fp[768 + tid]);
            float4 pb;
            pb.x = wl[65536 + tid];
            pb.y = wl[65792 + tid];
            pb.z = (l == 2) ? w[136192 + 2 * tid]     : 0.0f;
            pb.w = (l == 2) ? w[136192 + 2 * tid + 1] : 0.0f;
            *(float4*)&par[PF_FILMI + tid * 8]     = pa;
            *(float4*)&par[PF_FILMI + tid * 8 + 4] = pb;
        }

        float acc[2][4][4];
        #pragma unroll
        for (int mi = 0; mi < 2; ++mi)
            #pragma unroll
            for (int n8 = 0; n8 < 4; ++n8)
                #pragma unroll
                for (int q = 0; q < 4; ++q) acc[mi][n8][q] = 0.0f;

        #pragma unroll 1
        for (int item = 0; item < 8; ++item) {
            int g = (l - 1) * 8 + item;
            int buf = g & 1;
            if (g < 15) load_chunk_g(g + 1);

            u32 bbuf = smb + SM_B + (u32)buf * 16384;
            #pragma unroll
            for (int ks = 0; ks < 2; ++ks) {
                int k16 = item * 2 + ks;
                u32 a[2][4];
                #pragma unroll
                for (int mi = 0; mi < 2; ++mi)
                    lds128(a[mi][0], a[mi][1], a[mi][2], a[mi][3],
                           smb + SM_A + (u32)((mi * 16 + k16) * 32 + lid) * 16);
                u32 bh[2][4];
                #pragma unroll
                for (int nt = 0; nt < 2; ++nt) {
                    u32 off = (u32)((ks * 16 + wid * 2 + nt) * 32 + lid) * 16;
                    lds128(bh[nt][0], bh[nt][1], bh[nt][2], bh[nt][3], bbuf + off);
                }
                #pragma unroll
                for (int mi = 0; mi < 2; ++mi)
                    #pragma unroll
                    for (int n8 = 0; n8 < 4; ++n8) {
                        int nt = n8 >> 1, pp = (n8 & 1) * 2;
                        mmaf16(acc[mi][n8][0], acc[mi][n8][1], acc[mi][n8][2], acc[mi][n8][3],
                               a[mi][0], a[mi][1], a[mi][2], a[mi][3],
                               bh[nt][pp], bh[nt][pp + 1]);
                    }
            }
            CP_WAIT0();
            __syncthreads();
        }

        if (l == 2) {
            if (tid < 64) par[PF_RED + tid] = 0.0f;
            #pragma unroll
            for (int i = 0; i < 4; ++i) { ps0[i] = 0.0f; ps1[i] = 0.0f; }
            __syncthreads();
        }

        // ---- epilogue: FiLM + softplus (vectorized params) ----
        #pragma unroll
        for (int n8 = 0; n8 < 4; ++n8) {
            int col0 = wid * 32 + n8 * 8 + (lid & 3) * 2;
            float4 fa0 = *(float4*)&par[PF_FILMI + col0 * 8];
            float4 fb0 = *(float4*)&par[PF_FILMI + col0 * 8 + 4];
            float4 fa1 = *(float4*)&par[PF_FILMI + col0 * 8 + 8];
            float4 fb1 = *(float4*)&par[PF_FILMI + col0 * 8 + 12];
            int k16n = wid * 2 + (n8 >> 1);     // next-layer k16 of this col pair
            #pragma unroll
            for (int mi = 0; mi < 2; ++mi) {
                #pragma unroll
                for (int rh = 0; rh < 2; ++rh) {
                    int row = mi * 16 + (lid >> 2) + rh * 8;
                    float4 rp = *(float4*)&par[PF_ROWP + row * 4];
                    float v0 = acc[mi][n8][rh * 2 + 0];
                    float v1 = acc[mi][n8][rh * 2 + 1];
                    v0 += fa0.x + rp.y * fb0.x + rp.z * fb0.y;
                    v1 += fa1.x + rp.y * fb1.x + rp.z * fb1.y;
                    float s0 = sigmoid_ht(rp.x * fa0.y + fa0.z);
                    float s1 = sigmoid_ht(rp.x * fa1.y + fa1.z);
                    v0 = s0 * v0 + rp.x * fa0.w;
                    v1 = s1 * v1 + rp.x * fa1.w;
                    v0 = softplusf_fast(v0);
                    v1 = softplusf_fast(v1);
                    if (l == 1) {
                        u32 off = (u32)((mi * 16 + k16n) * 32 + lid) * 16
                                + (u32)(rh + 2 * (n8 & 1)) * 4;
                        *(u32*)(smc + SM_A + off) = pack_h2(v0, v1);
                    } else {
                        ps0[mi * 2 + rh] = fmaf(v0, fb0.z, fmaf(v1, fb1.z, ps0[mi * 2 + rh]));
                        ps1[mi * 2 + rh] = fmaf(v0, fb0.w, fmaf(v1, fb1.w, ps1[mi * 2 + rh]));
                    }
                }
            }
        }
        __syncthreads();
    }

    // ---- layer-3 reduction via shared atomics ----
    #pragma unroll
    for (int mi = 0; mi < 2; ++mi)
        #pragma unroll
        for (int rh = 0; rh < 2; ++rh) {
            int p = mi * 16 + (lid >> 2) + rh * 8;
            atomicAdd(&par[PF_RED + p * 2 + 0], ps0[mi * 2 + rh]);
            atomicAdd(&par[PF_RED + p * 2 + 1], ps1[mi * 2 + rh]);
        }
    __syncthreads();

    if (tid < 64) {
        int p = tid >> 1;
        int o = tid & 1;
        float4 rp = *(float4*)&par[PF_ROWP + p * 4];
        float s = par[PF_RED + p * 2 + o];
        s += rp.y * par[PF_W3T + o] + rp.z * par[PF_W3T + 2 + o];
        float v = s + par[PF_W3T + 4 + o];
        float g = sigmoid_ht(0.5f * (rp.x * par[PF_W3T + 6 + o] + par[PF_W3T + 8 + o]));
        v = g * v + rp.x * par[PF_W3T + 10 + o];
        out_g[((size_t)b * NN + p0 + p) * 2 + o] = v;
    }
}

extern "C" void kernel_launch(void* const* d_in, const int* in_sizes, int n_in,
                              void* d_out, int out_size) {
    (void)in_sizes; (void)n_in; (void)out_size;
    const float* ctx = (const float*)d_in[0];
    const float* y   = (const float*)d_in[1];
    const float* yp  = (const float*)d_in[2];
    const float* tnw = (const float*)d_in[3];
    float* out = (float*)d_out;

    prep_weights_kernel<<<128, 256>>>(tnw);

    cudaFuncSetAttribute(ode_hypernet_mma_kernel,
                         cudaFuncAttributeMaxDynamicSharedMemorySize, SMEM_TOTAL);
    dim3 grid(NN / TP, BB);   // (64, 64)
    ode_hypernet_mma_kernel<<<grid, 256, SMEM_TOTAL>>>(ctx, y, yp, tnw, out);
}

// round 14
// speedup vs baseline: 1.2372x; 1.2372x over previous
#include <cuda_runtime.h>
#include <cuda_fp16.h>
#include <cstdint>

typedef unsigned int u32;

// ---------------- problem constants ----------------
#define BB 64
#define NN 2048
#define TW 136716
#define TP 64

// ---------------- smem layout (bytes) ----------------
#define SM_A   0          // A fp16 frag-major: [4 m16][16 k16][32 lid][16B] = 32768
#define SM_B   32768      // 3 bufs x 16384 (1 kc each)
#define SM_PAR 81920
// float offsets inside PAR
#define PF_FILMI 0        // [256 cols][8]: bi, wsc/2, bsc/2, wsh, wt0, wt1, w30, w31
                          // (layer0: [0..1023] film0 [col][4]; [1024..2047] W0I [col][4])
#define PF_ROWP  2048     // [64][4]: cc, yp0, yp1, 0
#define PF_YS    2304     // [128]
#define PF_W3T   2432     // [16]
#define PF_RED   2448     // [128]
#define PAR_FLOATS 2576
#define SMEM_TOTAL (81920 + PAR_FLOATS*4)   // 92224

// precomputed fp16 weights, frag-major: [b][l][kc 8][4096 u32] = 16 MB used
__device__ uint4 g_wbf[2097152];

// ---------------- helpers ----------------
__device__ __forceinline__ u32 smem_u32(const void* p) {
    u32 a; asm("{ .reg .u64 t; cvta.to.shared.u64 t, %1; cvt.u32.u64 %0, t; }" : "=r"(a) : "l"(p));
    return a;
}
__device__ __forceinline__ u32 pack_h2(float a, float b) {
    __half2 t = __floats2half2_rn(a, b);
    return *reinterpret_cast<u32*>(&t);
}
__device__ __forceinline__ void lds128(u32& r0, u32& r1, u32& r2, u32& r3, u32 addr) {
    asm volatile("ld.shared.v4.u32 {%0,%1,%2,%3}, [%4];"
                 : "=r"(r0), "=r"(r1), "=r"(r2), "=r"(r3) : "r"(addr));
}
__device__ __forceinline__ void mmaf16(float& c0, float& c1, float& c2, float& c3,
                                       u32 a0, u32 a1, u32 a2, u32 a3,
                                       u32 b0, u32 b1) {
    asm volatile("mma.sync.aligned.m16n8k16.row.col.f32.f16.f16.f32 "
                 "{%0,%1,%2,%3}, {%4,%5,%6,%7}, {%8,%9}, {%0,%1,%2,%3};"
                 : "+f"(c0), "+f"(c1), "+f"(c2), "+f"(c3)
                 : "r"(a0), "r"(a1), "r"(a2), "r"(a3), "r"(b0), "r"(b1));
}
__device__ __forceinline__ void cpasync16(u32 dst, const void* src) {
    asm volatile("cp.async.cg.shared.global [%0], [%1], 16;" :: "r"(dst), "l"(src));
}
#define CP_COMMIT() asm volatile("cp.async.commit_group;" ::: "memory")
#define CP_WAIT1()  asm volatile("cp.async.wait_group 1;" ::: "memory")

__device__ __forceinline__ float ex2f(float x){ float r; asm("ex2.approx.ftz.f32 %0, %1;" : "=f"(r) : "f"(x)); return r; }
__device__ __forceinline__ float tanhf_fast(float x){ float r; asm("tanh.approx.f32 %0, %1;" : "=f"(r) : "f"(x)); return r; }
__device__ __forceinline__ float sigmoid_ht(float halfarg) {
    return fmaf(tanhf_fast(halfarg), 0.5f, 0.5f);
}
// softplus(x) = max(x,0) + ln(1+e), e = 2^(-|x|*log2e); ln(1+e) via deg-5 minimax
// (A&S 4.1.43, |err| < 1e-5 on e in [0,1]); no lg2 MUFU.
__device__ __forceinline__ float softplusf_fast(float x) {
    float e = ex2f(-1.4426950408889634f * fabsf(x));
    float p = fmaf(0.03215845f, e, -0.13606275f);
    p = fmaf(p, e, 0.28947478f);
    p = fmaf(p, e, -0.49190896f);
    p = fmaf(p, e, 0.99949556f);
    return fmaxf(x, 0.0f) + p * e;
}

// ---------------- prep: f32 W -> fp16 frag-major image ----------------
__global__ __launch_bounds__(256)
void prep_weights_kernel(const float* __restrict__ tnw)
{
    __shared__ float s[32][257];
    int bl = blockIdx.x;           // 0..127
    int l = bl & 1, b = bl >> 1;
    const float* wl = tnw + (size_t)b * TW + (l == 0 ? 2048 : 69120);
    int t = threadIdx.x;
    u32* gh = (u32*)g_wbf;

    for (int kc = 0; kc < 8; ++kc) {
        __syncthreads();
        #pragma unroll
        for (int j = 0; j < 32; ++j) {
            int idx = t + j * 256;               // 8192 floats
            int r = idx >> 8, c = idx & 255;
            s[r][c] = wl[(size_t)(kc * 32 + r) * 256 + c];
        }
        __syncthreads();
        size_t base0 = ((size_t)(b * 2 + l) * 8 + kc) * 4096;
        #pragma unroll
        for (int j = 0; j < 16; ++j) {
            int idx = t + j * 256;               // 0..4095
            int reg = idx & 3;
            int lid = (idx >> 2) & 31;
            int n16 = (idx >> 7) & 15;
            int ks  = idx >> 11;
            int koff = ks * 16 + 2 * (lid & 3) + 8 * (reg & 1);
            int n = n16 * 16 + (lid >> 2) + 8 * (reg >> 1);
            gh[base0 + idx] = pack_h2(s[koff][n], s[koff + 1][n]);
        }
    }
}

// ---------------- main kernel: 256 threads, 8 warps (64x32 warp tiles), 2 CTAs/SM ----------------
__global__ __launch_bounds__(256, 2)
void ode_hypernet_mma_kernel(const float* __restrict__ ctx_g,
                             const float* __restrict__ y_g,
                             const float* __restrict__ yp_g,
                             const float* __restrict__ tnw_g,
                             float* __restrict__ out_g)
{
    extern __shared__ char smc[];
    float* par = (float*)(smc + SM_PAR);
    const u32 smb = smem_u32(smc);

    const int tid = threadIdx.x;
    const int lid = tid & 31;
    const int wid = tid >> 5;        // = wn, 8 warps x 32 cols
    const int b  = blockIdx.y;
    const int p0 = blockIdx.x * TP;
    const float* w = tnw_g + (size_t)b * TW;
    const char* gw = (const char*)g_wbf;

    // item stream: g 0..15 -> layer (g>>3), kc (g&7), buf (g%3); 16KB per item
    auto load_chunk_g = [&](int g) {
        size_t src = ((size_t)(b * 2 + (g >> 3)) * 8 + (size_t)(g & 7)) * 16384;
        u32 dbase = smb + SM_B + (u32)(g % 3) * 16384;
        #pragma unroll
        for (int i = 0; i < 4; ++i) {
            u32 off = (u32)(tid + i * 256) * 16;
            cpasync16(dbase + off, gw + src + off);
        }
        CP_COMMIT();
    };

    // ---- initial loads ----
    if (tid < 64) {
        size_t base = ((size_t)b * NN + p0 + tid) * 2;
        float4 rp = make_float4(ctx_g[(size_t)b * NN + p0 + tid],
                                yp_g[base + 0], yp_g[base + 1], 0.0f);
        *(float4*)&par[PF_ROWP + tid * 4] = rp;
    }
    if (tid < 128) par[PF_YS + tid] = y_g[((size_t)b * NN + p0) * 2 + tid];
    {
        // film0 [col][4] (wsc,bsc pre-halved) and W0I [col][4]
        float4 f0 = make_float4(w[1024 + tid], w[1280 + tid] * 0.5f,
                                w[1536 + tid] * 0.5f, w[1792 + tid]);
        float4 w0 = make_float4(w[tid], w[256 + tid], w[512 + tid], w[768 + tid]);
        *(float4*)&par[PF_FILMI + tid * 4] = f0;
        *(float4*)&par[PF_FILMI + 1024 + tid * 4] = w0;
    }
    if (tid < 16)
        par[PF_W3T + tid] = (tid < 4) ? w[136192 + 512 + tid]
                          : (tid < 12 ? w[136708 + tid - 4] : 0.0f);

    load_chunk_g(0);
    load_chunk_g(1);
    __syncthreads();

    // ---- layer 0 (SIMT): 4 -> 256, FiLM + softplus, write A fp16 frag-major ----
    {
        int p = tid & 63;
        int h2 = tid >> 6;           // 0..3, 64 channels each
        float4 rp = *(float4*)&par[PF_ROWP + p * 4];
        float cc = rp.x, q0 = rp.y, q1 = rp.z;
        float y0 = par[PF_YS + 2 * p], y1 = par[PF_YS + 2 * p + 1];
        int m16 = p >> 4;
        int plid4 = (p & 7) * 4;
        int preg = (p >> 3) & 1;
        #pragma unroll 4
        for (int j = 0; j < 32; ++j) {
            int ch = h2 * 64 + 2 * j;
            float4 wa = *(float4*)&par[PF_FILMI + 1024 + ch * 4];
            float4 wb = *(float4*)&par[PF_FILMI + 1024 + (ch + 1) * 4];
            float4 f0 = *(float4*)&par[PF_FILMI + ch * 4];
            float4 f1 = *(float4*)&par[PF_FILMI + (ch + 1) * 4];
            float v0 = y0 * wa.x + y1 * wa.y + q0 * wa.z + q1 * wa.w + f0.x;
            float v1 = y0 * wb.x + y1 * wb.y + q0 * wb.z + q1 * wb.w + f1.x;
            float s0 = sigmoid_ht(cc * f0.y + f0.z);
            float s1 = sigmoid_ht(cc * f1.y + f1.z);
            v0 = s0 * v0 + cc * f0.w;
            v1 = s1 * v1 + cc * f1.w;
            v0 = softplusf_fast(v0);
            v1 = softplusf_fast(v1);
            int k16 = ch >> 4;
            int flid = plid4 + (j & 3);
            int reg  = preg + 2 * ((j >> 2) & 1);
            u32 off = (u32)((m16 * 16 + k16) * 32 + flid) * 16 + (u32)reg * 4;
            *(u32*)(smc + SM_A + off) = pack_h2(v0, v1);
        }
    }
    __syncthreads();   // A ready; FILMI(l0) reads done before l1 overwrite

    float ps0[8], ps1[8];            // layer-3 partials (mi x rh)

    #pragma unroll 1
    for (int l = 1; l <= 2; ++l) {
        const float* wl = w + ((l == 1) ? 2048 : 69120);
        const float* fp = wl + 66048;
        {
            // FILMI [col][8]: bi, wsc/2, bsc/2, wsh, wt0, wt1, w30, w31
            float4 pa = make_float4(fp[tid], fp[256 + tid] * 0.5f,
                                    fp[512 + tid] * 0.5f, fp[768 + tid]);
            float4 pb;
            pb.x = wl[65536 + tid];
            pb.y = wl[65792 + tid];
            pb.z = (l == 2) ? w[136192 + 2 * tid]     : 0.0f;
            pb.w = (l == 2) ? w[136192 + 2 * tid + 1] : 0.0f;
            *(float4*)&par[PF_FILMI + tid * 8]     = pa;
            *(float4*)&par[PF_FILMI + tid * 8 + 4] = pb;
        }

        float acc[4][4][4];
        #pragma unroll
        for (int mi = 0; mi < 4; ++mi)
            #pragma unroll
            for (int n8 = 0; n8 < 4; ++n8)
                #pragma unroll
                for (int q = 0; q < 4; ++q) acc[mi][n8][q] = 0.0f;

        #pragma unroll 1
        for (int item = 0; item < 8; ++item) {
            int g = (l - 1) * 8 + item;
            CP_WAIT1();              // group g complete (<=1 newer pending)
            __syncthreads();         // everyone's copies visible; buf (g-1) reads done
            if (g < 14) load_chunk_g(g + 2);

            u32 bbuf = smb + SM_B + (u32)(g % 3) * 16384;
            #pragma unroll
            for (int ks = 0; ks < 2; ++ks) {
                int k16 = item * 2 + ks;
                u32 a[4][4];
                #pragma unroll
                for (int mi = 0; mi < 4; ++mi)
                    lds128(a[mi][0], a[mi][1], a[mi][2], a[mi][3],
                           smb + SM_A + (u32)((mi * 16 + k16) * 32 + lid) * 16);
                u32 bh[2][4];
                #pragma unroll
                for (int nt = 0; nt < 2; ++nt) {
                    u32 off = (u32)((ks * 16 + wid * 2 + nt) * 32 + lid) * 16;
                    lds128(bh[nt][0], bh[nt][1], bh[nt][2], bh[nt][3], bbuf + off);
                }
                #pragma unroll
                for (int mi = 0; mi < 4; ++mi)
                    #pragma unroll
                    for (int n8 = 0; n8 < 4; ++n8) {
                        int nt = n8 >> 1, pp = (n8 & 1) * 2;
                        mmaf16(acc[mi][n8][0], acc[mi][n8][1], acc[mi][n8][2], acc[mi][n8][3],
                               a[mi][0], a[mi][1], a[mi][2], a[mi][3],
                               bh[nt][pp], bh[nt][pp + 1]);
                    }
            }
        }
        __syncthreads();   // all reads of A / last buf done before epilogue writes

        if (l == 2) {
            if (tid < 128) par[PF_RED + tid] = 0.0f;
            #pragma unroll
            for (int i = 0; i < 8; ++i) { ps0[i] = 0.0f; ps1[i] = 0.0f; }
            __syncthreads();
        }

        // ---- epilogue: FiLM + softplus (vectorized params) ----
        #pragma unroll
        for (int n8 = 0; n8 < 4; ++n8) {
            int col0 = wid * 32 + n8 * 8 + (lid & 3) * 2;
            float4 fa0 = *(float4*)&par[PF_FILMI + col0 * 8];
            float4 fb0 = *(float4*)&par[PF_FILMI + col0 * 8 + 4];
            float4 fa1 = *(float4*)&par[PF_FILMI + col0 * 8 + 8];
            float4 fb1 = *(float4*)&par[PF_FILMI + col0 * 8 + 12];
            int k16n = wid * 2 + (n8 >> 1);     // next-layer k16 of this col pair
            #pragma unroll
            for (int mi = 0; mi < 4; ++mi) {
                #pragma unroll
                for (int rh = 0; rh < 2; ++rh) {
                    int row = mi * 16 + (lid >> 2) + rh * 8;
                    float4 rp = *(float4*)&par[PF_ROWP + row * 4];
                    float v0 = acc[mi][n8][rh * 2 + 0];
                    float v1 = acc[mi][n8][rh * 2 + 1];
                    v0 += fa0.x + rp.y * fb0.x + rp.z * fb0.y;
                    v1 += fa1.x + rp.y * fb1.x + rp.z * fb1.y;
                    float s0 = sigmoid_ht(rp.x * fa0.y + fa0.z);
                    float s1 = sigmoid_ht(rp.x * fa1.y + fa1.z);
                    v0 = s0 * v0 + rp.x * fa0.w;
                    v1 = s1 * v1 + rp.x * fa1.w;
                    v0 = softplusf_fast(v0);
                    v1 = softplusf_fast(v1);
                    if (l == 1) {
                        u32 off = (u32)((mi * 16 + k16n) * 32 + lid) * 16
                                + (u32)(rh + 2 * (n8 & 1)) * 4;
                        *(u32*)(smc + SM_A + off) = pack_h2(v0, v1);
                    } else {
                        ps0[mi * 2 + rh] = fmaf(v0, fb0.z, fmaf(v1, fb1.z, ps0[mi * 2 + rh]));
                        ps1[mi * 2 + rh] = fmaf(v0, fb0.w, fmaf(v1, fb1.w, ps1[mi * 2 + rh]));
                    }
                }
            }
        }
        __syncthreads();
    }

    // ---- layer-3 reduction: shuffle over the 4 lanes sharing a row, then atomics ----
    #pragma unroll
    for (int mi = 0; mi < 4; ++mi)
        #pragma unroll
        for (int rh = 0; rh < 2; ++rh) {
            float s0 = ps0[mi * 2 + rh];
            float s1 = ps1[mi * 2 + rh];
            s0 += __shfl_xor_sync(0xffffffffu, s0, 1);
            s0 += __shfl_xor_sync(0xffffffffu, s0, 2);
            s1 += __shfl_xor_sync(0xffffffffu, s1, 1);
            s1 += __shfl_xor_sync(0xffffffffu, s1, 2);
            if ((lid & 3) == 0) {
                int p = mi * 16 + (lid >> 2) + rh * 8;
                atomicAdd(&par[PF_RED + p * 2 + 0], s0);
                atomicAdd(&par[PF_RED + p * 2 + 1], s1);
            }
        }
    __syncthreads();

    if (tid < 128) {
        int p = tid >> 1;
        int o = tid & 1;
        float4 rp = *(float4*)&par[PF_ROWP + p * 4];
        float s = par[PF_RED + p * 2 + o];
        s += rp.y * par[PF_W3T + o] + rp.z * par[PF_W3T + 2 + o];
        float v = s + par[PF_W3T + 4 + o];
        float g = sigmoid_ht(0.5f * (rp.x * par[PF_W3T + 6 + o] + par[PF_W3T + 8 + o]));
        v = g * v + rp.x * par[PF_W3T + 10 + o];
        out_g[((size_t)b * NN + p0 + p) * 2 + o] = v;
    }
}

extern "C" void kernel_launch(void* const* d_in, const int* in_sizes, int n_in,
                              void* d_out, int out_size) {
    (void)in_sizes; (void)n_in; (void)out_size;
    const float* ctx = (const float*)d_in[0];
    const float* y   = (const float*)d_in[1];
    const float* yp  = (const float*)d_in[2];
    const float* tnw = (const float*)d_in[3];
    float* out = (float*)d_out;

    prep_weights_kernel<<<128, 256>>>(tnw);

    cudaFuncSetAttribute(ode_hypernet_mma_kernel,
                         cudaFuncAttributeMaxDynamicSharedMemorySize, SMEM_TOTAL);
    dim3 grid(NN / TP, BB);   // (32, 64)
    ode_hypernet_mma_kernel<<<grid, 256, SMEM_TOTAL>>>(ctx, y, yp, tnw, out);
}

// round 15
// speedup vs baseline: 1.3436x; 1.0860x over previous
#include <cuda_runtime.h>
#include <cuda_fp16.h>
#include <cstdint>

typedef unsigned int u32;

// ---------------- problem constants ----------------
#define BB 64
#define NN 2048
#define TW 136716
#define TP 64

// ---------------- smem layout (bytes) ----------------
#define SM_A   0          // A fp16 frag-major: [4 m16][16 k16][32 lid][16B] = 32768
#define SM_B   32768      // 3 bufs x 16384 (1 kc each); per-warp-owned regions
#define SM_PAR 81920
// float offsets inside PAR
#define PF_FILMI 0        // [256 cols][8]: bi, wsc/2, bsc/2, wsh, wt0, wt1, w30, w31
                          // (layer0: [0..1023] film0 [col][4]; [1024..2047] W0I [col][4])
#define PF_ROWP  2048     // [64][4]: cc, yp0, yp1, 0
#define PF_YS    2304     // [128]
#define PF_W3T   2432     // [16]
#define PF_RED   2448     // [128]
#define PAR_FLOATS 2576
#define SMEM_TOTAL (81920 + PAR_FLOATS*4)   // 92224

// precomputed fp16 weights, frag-major: [b][l][kc 8][4096 u32] = 16 MB used
__device__ uint4 g_wbf[2097152];

// ---------------- helpers ----------------
__device__ __forceinline__ u32 smem_u32(const void* p) {
    u32 a; asm("{ .reg .u64 t; cvta.to.shared.u64 t, %1; cvt.u32.u64 %0, t; }" : "=r"(a) : "l"(p));
    return a;
}
__device__ __forceinline__ u32 pack_h2(float a, float b) {
    __half2 t = __floats2half2_rn(a, b);
    return *reinterpret_cast<u32*>(&t);
}
__device__ __forceinline__ void lds128(u32& r0, u32& r1, u32& r2, u32& r3, u32 addr) {
    asm volatile("ld.shared.v4.u32 {%0,%1,%2,%3}, [%4];"
                 : "=r"(r0), "=r"(r1), "=r"(r2), "=r"(r3) : "r"(addr));
}
__device__ __forceinline__ void mmaf16(float& c0, float& c1, float& c2, float& c3,
                                       u32 a0, u32 a1, u32 a2, u32 a3,
                                       u32 b0, u32 b1) {
    asm volatile("mma.sync.aligned.m16n8k16.row.col.f32.f16.f16.f32 "
                 "{%0,%1,%2,%3}, {%4,%5,%6,%7}, {%8,%9}, {%0,%1,%2,%3};"
                 : "+f"(c0), "+f"(c1), "+f"(c2), "+f"(c3)
                 : "r"(a0), "r"(a1), "r"(a2), "r"(a3), "r"(b0), "r"(b1));
}
__device__ __forceinline__ void cpasync16(u32 dst, const void* src) {
    asm volatile("cp.async.cg.shared.global [%0], [%1], 16;" :: "r"(dst), "l"(src));
}
#define CP_COMMIT() asm volatile("cp.async.commit_group;" ::: "memory")
#define CP_WAIT1()  asm volatile("cp.async.wait_group 1;" ::: "memory")

__device__ __forceinline__ float ex2f(float x){ float r; asm("ex2.approx.ftz.f32 %0, %1;" : "=f"(r) : "f"(x)); return r; }
__device__ __forceinline__ float tanhf_fast(float x){ float r; asm("tanh.approx.f32 %0, %1;" : "=f"(r) : "f"(x)); return r; }
__device__ __forceinline__ float sigmoid_ht(float halfarg) {
    return fmaf(tanhf_fast(halfarg), 0.5f, 0.5f);
}
// softplus(x) = max(x,0) + ln(1+e), e = 2^(-|x|*log2e); ln(1+e) via deg-5 minimax
__device__ __forceinline__ float softplusf_fast(float x) {
    float e = ex2f(-1.4426950408889634f * fabsf(x));
    float p = fmaf(0.03215845f, e, -0.13606275f);
    p = fmaf(p, e, 0.28947478f);
    p = fmaf(p, e, -0.49190896f);
    p = fmaf(p, e, 0.99949556f);
    return fmaxf(x, 0.0f) + p * e;
}

// ---------------- prep: f32 W -> fp16 frag-major image ----------------
__global__ __launch_bounds__(256)
void prep_weights_kernel(const float* __restrict__ tnw)
{
    __shared__ float s[32][257];
    int bl = blockIdx.x;           // 0..127
    int l = bl & 1, b = bl >> 1;
    const float* wl = tnw + (size_t)b * TW + (l == 0 ? 2048 : 69120);
    int t = threadIdx.x;
    u32* gh = (u32*)g_wbf;

    for (int kc = 0; kc < 8; ++kc) {
        __syncthreads();
        #pragma unroll
        for (int j = 0; j < 32; ++j) {
            int idx = t + j * 256;               // 8192 floats
            int r = idx >> 8, c = idx & 255;
            s[r][c] = wl[(size_t)(kc * 32 + r) * 256 + c];
        }
        __syncthreads();
        size_t base0 = ((size_t)(b * 2 + l) * 8 + kc) * 4096;
        #pragma unroll
        for (int j = 0; j < 16; ++j) {
            int idx = t + j * 256;               // 0..4095
            int reg = idx & 3;
            int lid = (idx >> 2) & 31;
            int n16 = (idx >> 7) & 15;
            int ks  = idx >> 11;
            int koff = ks * 16 + 2 * (lid & 3) + 8 * (reg & 1);
            int n = n16 * 16 + (lid >> 2) + 8 * (reg >> 1);
            gh[base0 + idx] = pack_h2(s[koff][n], s[koff + 1][n]);
        }
    }
}

// ---------------- main kernel: 256 threads, 8 warps (64x32 warp tiles), 2 CTAs/SM ----------------
__global__ __launch_bounds__(256, 2)
void ode_hypernet_mma_kernel(const float* __restrict__ ctx_g,
                             const float* __restrict__ y_g,
                             const float* __restrict__ yp_g,
                             const float* __restrict__ tnw_g,
                             float* __restrict__ out_g)
{
    extern __shared__ char smc[];
    float* par = (float*)(smc + SM_PAR);
    const u32 smb = smem_u32(smc);

    const int tid = threadIdx.x;
    const int lid = tid & 31;
    const int wid = tid >> 5;        // = wn, 8 warps x 32 cols
    const int b  = blockIdx.y;
    const int p0 = blockIdx.x * TP;
    const float* w = tnw_g + (size_t)b * TW;
    const char* gw = (const char*)g_wbf;

    // per-warp B copy: each warp copies EXACTLY the region it reads
    // (blocks (ks,nt) for nt = wid*2, wid*2+1; 2KB/warp/item), so its own
    // cp.async.wait_group suffices for visibility -> NO per-item barrier.
    auto load_chunk_g = [&](int g) {
        size_t src = ((size_t)(b * 2 + (g >> 3)) * 8 + (size_t)(g & 7)) * 16384;
        u32 dbase = smb + SM_B + (u32)(g % 3) * 16384;
        #pragma unroll
        for (int ks = 0; ks < 2; ++ks)
            #pragma unroll
            for (int nt = 0; nt < 2; ++nt) {
                u32 off = (u32)((ks * 16 + wid * 2 + nt) * 32 + lid) * 16;
                cpasync16(dbase + off, gw + src + off);
            }
        CP_COMMIT();
    };

    // ---- initial loads ----
    if (tid < 64) {
        size_t base = ((size_t)b * NN + p0 + tid) * 2;
        float4 rp = make_float4(ctx_g[(size_t)b * NN + p0 + tid],
                                yp_g[base + 0], yp_g[base + 1], 0.0f);
        *(float4*)&par[PF_ROWP + tid * 4] = rp;
    }
    if (tid < 128) par[PF_YS + tid] = y_g[((size_t)b * NN + p0) * 2 + tid];
    {
        // film0 [col][4] (wsc,bsc pre-halved) and W0I [col][4]
        float4 f0 = make_float4(w[1024 + tid], w[1280 + tid] * 0.5f,
                                w[1536 + tid] * 0.5f, w[1792 + tid]);
        float4 w0 = make_float4(w[tid], w[256 + tid], w[512 + tid], w[768 + tid]);
        *(float4*)&par[PF_FILMI + tid * 4] = f0;
        *(float4*)&par[PF_FILMI + 1024 + tid * 4] = w0;
    }
    if (tid < 16)
        par[PF_W3T + tid] = (tid < 4) ? w[136192 + 512 + tid]
                          : (tid < 12 ? w[136708 + tid - 4] : 0.0f);

    load_chunk_g(0);
    load_chunk_g(1);
    __syncthreads();

    // ---- layer 0 (SIMT): 4 -> 256, FiLM + softplus, write A fp16 frag-major ----
    {
        int p = tid & 63;
        int h2 = tid >> 6;           // 0..3, 64 channels each
        float4 rp = *(float4*)&par[PF_ROWP + p * 4];
        float cc = rp.x, q0 = rp.y, q1 = rp.z;
        float y0 = par[PF_YS + 2 * p], y1 = par[PF_YS + 2 * p + 1];
        int m16 = p >> 4;
        int plid4 = (p & 7) * 4;
        int preg = (p >> 3) & 1;
        #pragma unroll 4
        for (int j = 0; j < 32; ++j) {
            int ch = h2 * 64 + 2 * j;
            float4 wa = *(float4*)&par[PF_FILMI + 1024 + ch * 4];
            float4 wb = *(float4*)&par[PF_FILMI + 1024 + (ch + 1) * 4];
            float4 f0 = *(float4*)&par[PF_FILMI + ch * 4];
            float4 f1 = *(float4*)&par[PF_FILMI + (ch + 1) * 4];
            float v0 = y0 * wa.x + y1 * wa.y + q0 * wa.z + q1 * wa.w + f0.x;
            float v1 = y0 * wb.x + y1 * wb.y + q0 * wb.z + q1 * wb.w + f1.x;
            float s0 = sigmoid_ht(cc * f0.y + f0.z);
            float s1 = sigmoid_ht(cc * f1.y + f1.z);
            v0 = s0 * v0 + cc * f0.w;
            v1 = s1 * v1 + cc * f1.w;
            v0 = softplusf_fast(v0);
            v1 = softplusf_fast(v1);
            int k16 = ch >> 4;
            int flid = plid4 + (j & 3);
            int reg  = preg + 2 * ((j >> 2) & 1);
            u32 off = (u32)((m16 * 16 + k16) * 32 + flid) * 16 + (u32)reg * 4;
            *(u32*)(smc + SM_A + off) = pack_h2(v0, v1);
        }
    }
    __syncthreads();   // A ready; FILMI(l0) reads done before l1 overwrite

    float ps0[8], ps1[8];            // layer-3 partials (mi x rh)

    #pragma unroll 1
    for (int l = 1; l <= 2; ++l) {
        const float* wl = w + ((l == 1) ? 2048 : 69120);
        const float* fp = wl + 66048;
        {
            // FILMI [col][8]: bi, wsc/2, bsc/2, wsh, wt0, wt1, w30, w31
            float4 pa = make_float4(fp[tid], fp[256 + tid] * 0.5f,
                                    fp[512 + tid] * 0.5f, fp[768 + tid]);
            float4 pb;
            pb.x = wl[65536 + tid];
            pb.y = wl[65792 + tid];
            pb.z = (l == 2) ? w[136192 + 2 * tid]     : 0.0f;
            pb.w = (l == 2) ? w[136192 + 2 * tid + 1] : 0.0f;
            *(float4*)&par[PF_FILMI + tid * 8]     = pa;
            *(float4*)&par[PF_FILMI + tid * 8 + 4] = pb;
        }

        float acc[4][4][4];
        #pragma unroll
        for (int mi = 0; mi < 4; ++mi)
            #pragma unroll
            for (int n8 = 0; n8 < 4; ++n8)
                #pragma unroll
                for (int q = 0; q < 4; ++q) acc[mi][n8][q] = 0.0f;

        // barrier-free K-stream: each warp waits only on ITS OWN cp groups
        #pragma unroll 1
        for (int item = 0; item < 8; ++item) {
            int g = (l - 1) * 8 + item;
            CP_WAIT1();              // own group g complete (<=1 newer pending)
            if (g < 14) load_chunk_g(g + 2);

            u32 bbuf = smb + SM_B + (u32)(g % 3) * 16384;
            #pragma unroll
            for (int ks = 0; ks < 2; ++ks) {
                int k16 = item * 2 + ks;
                u32 a[4][4];
                #pragma unroll
                for (int mi = 0; mi < 4; ++mi)
                    lds128(a[mi][0], a[mi][1], a[mi][2], a[mi][3],
                           smb + SM_A + (u32)((mi * 16 + k16) * 32 + lid) * 16);
                u32 bh[2][4];
                #pragma unroll
                for (int nt = 0; nt < 2; ++nt) {
                    u32 off = (u32)((ks * 16 + wid * 2 + nt) * 32 + lid) * 16;
                    lds128(bh[nt][0], bh[nt][1], bh[nt][2], bh[nt][3], bbuf + off);
                }
                #pragma unroll
                for (int mi = 0; mi < 4; ++mi)
                    #pragma unroll
                    for (int n8 = 0; n8 < 4; ++n8) {
                        int nt = n8 >> 1, pp = (n8 & 1) * 2;
                        mmaf16(acc[mi][n8][0], acc[mi][n8][1], acc[mi][n8][2], acc[mi][n8][3],
                               a[mi][0], a[mi][1], a[mi][2], a[mi][3],
                               bh[nt][pp], bh[nt][pp + 1]);
                    }
            }
        }
        __syncthreads();   // all warps' reads of A done before epilogue overwrites A

        if (l == 2) {
            if (tid < 128) par[PF_RED + tid] = 0.0f;
            #pragma unroll
            for (int i = 0; i < 8; ++i) { ps0[i] = 0.0f; ps1[i] = 0.0f; }
            __syncthreads();
        }

        // ---- epilogue: FiLM + softplus (vectorized params) ----
        #pragma unroll
        for (int n8 = 0; n8 < 4; ++n8) {
            int col0 = wid * 32 + n8 * 8 + (lid & 3) * 2;
            float4 fa0 = *(float4*)&par[PF_FILMI + col0 * 8];
            float4 fb0 = *(float4*)&par[PF_FILMI + col0 * 8 + 4];
            float4 fa1 = *(float4*)&par[PF_FILMI + col0 * 8 + 8];
            float4 fb1 = *(float4*)&par[PF_FILMI + col0 * 8 + 12];
            int k16n = wid * 2 + (n8 >> 1);     // next-layer k16 of this col pair
            #pragma unroll
            for (int mi = 0; mi < 4; ++mi) {
                #pragma unroll
                for (int rh = 0; rh < 2; ++rh) {
                    int row = mi * 16 + (lid >> 2) + rh * 8;
                    float4 rp = *(float4*)&par[PF_ROWP + row * 4];
                    float v0 = acc[mi][n8][rh * 2 + 0];
                    float v1 = acc[mi][n8][rh * 2 + 1];
                    v0 += fa0.x + rp.y * fb0.x + rp.z * fb0.y;
                    v1 += fa1.x + rp.y * fb1.x + rp.z * fb1.y;
                    float s0 = sigmoid_ht(rp.x * fa0.y + fa0.z);
                    float s1 = sigmoid_ht(rp.x * fa1.y + fa1.z);
                    v0 = s0 * v0 + rp.x * fa0.w;
                    v1 = s1 * v1 + rp.x * fa1.w;
                    v0 = softplusf_fast(v0);
                    v1 = softplusf_fast(v1);
                    if (l == 1) {
                        u32 off = (u32)((mi * 16 + k16n) * 32 + lid) * 16
                                + (u32)(rh + 2 * (n8 & 1)) * 4;
                        *(u32*)(smc + SM_A + off) = pack_h2(v0, v1);
                    } else {
                        ps0[mi * 2 + rh] = fmaf(v0, fb0.z, fmaf(v1, fb1.z, ps0[mi * 2 + rh]));
                        ps1[mi * 2 + rh] = fmaf(v0, fb0.w, fmaf(v1, fb1.w, ps1[mi * 2 + rh]));
                    }
                }
            }
        }
        __syncthreads();
    }

    // ---- layer-3 reduction: shuffle over the 4 lanes sharing a row, then atomics ----
    #pragma unroll
    for (int mi = 0; mi < 4; ++mi)
        #pragma unroll
        for (int rh = 0; rh < 2; ++rh) {
            float s0 = ps0[mi * 2 + rh];
            float s1 = ps1[mi * 2 + rh];
            s0 += __shfl_xor_sync(0xffffffffu, s0, 1);
            s0 += __shfl_xor_sync(0xffffffffu, s0, 2);
            s1 += __shfl_xor_sync(0xffffffffu, s1, 1);
            s1 += __shfl_xor_sync(0xffffffffu, s1, 2);
            if ((lid & 3) == 0) {
                int p = mi * 16 + (lid >> 2) + rh * 8;
                atomicAdd(&par[PF_RED + p * 2 + 0], s0);
                atomicAdd(&par[PF_RED + p * 2 + 1], s1);
            }
        }
    __syncthreads();

    if (tid < 128) {
        int p = tid >> 1;
        int o = tid & 1;
        float4 rp = *(float4*)&par[PF_ROWP + p * 4];
        float s = par[PF_RED + p * 2 + o];
        s += rp.y * par[PF_W3T + o] + rp.z * par[PF_W3T + 2 + o];
        float v = s + par[PF_W3T + 4 + o];
        float g = sigmoid_ht(0.5f * (rp.x * par[PF_W3T + 6 + o] + par[PF_W3T + 8 + o]));
        v = g * v + rp.x * par[PF_W3T + 10 + o];
        out_g[((size_t)b * NN + p0 + p) * 2 + o] = v;
    }
}

extern "C" void kernel_launch(void* const* d_in, const int* in_sizes, int n_in,
                              void* d_out, int out_size) {
    (void)in_sizes; (void)n_in; (void)out_size;
    const float* ctx = (const float*)d_in[0];
    const float* y   = (const float*)d_in[1];
    const float* yp  = (const float*)d_in[2];
    const float* tnw = (const float*)d_in[3];
    float* out = (float*)d_out;

    prep_weights_kernel<<<128, 256>>>(tnw);

    cudaFuncSetAttribute(ode_hypernet_mma_kernel,
                         cudaFuncAttributeMaxDynamicSharedMemorySize, SMEM_TOTAL);
    dim3 grid(NN / TP, BB);   // (32, 64)
    ode_hypernet_mma_kernel<<<grid, 256, SMEM_TOTAL>>>(ctx, y, yp, tnw, out);
}

// round 16
// speedup vs baseline: 1.3843x; 1.0303x over previous
#include <cuda_runtime.h>
#include <cuda_fp16.h>
#include <cstdint>

typedef unsigned int u32;
typedef unsigned long long u64;

// ---------------- problem constants ----------------
#define BB 64
#define NN 2048
#define TW 136716
#define TP 64

// ---------------- smem layout (bytes) ----------------
#define SM_A   0          // A fp16 frag-major: [4 m16][16 k16][32 lid][16B] = 32768
#define SM_B   32768      // 3 bufs x 16384 (1 kc each); per-warp-owned regions
#define SM_PAR 81920
// float offsets inside PAR
#define PF_FILMI 0        // layers 1-2: [128 pairs][16]: bi01, wsc01/2, bsc01/2, wsh01,
                          //   wt0_01, wt1_01, w3(c0)01, w3(c1)01
                          // (layer0: [0..1023] film0 [col][4]; [1024..2047] W0I [col][4])
#define PF_ROWP  2048     // [64][4]: cc, yp0, yp1, 0
#define PF_YS    2304     // [128]
#define PF_W3T   2432     // [16]
#define PF_RED   2448     // [128]
#define PAR_FLOATS 2576
#define SMEM_TOTAL (81920 + PAR_FLOATS*4)   // 92224

// precomputed fp16 weights, frag-major: [b][l][kc 8][4096 u32] = 16 MB used
__device__ uint4 g_wbf[2097152];

// ---------------- helpers ----------------
__device__ __forceinline__ u32 smem_u32(const void* p) {
    u32 a; asm("{ .reg .u64 t; cvta.to.shared.u64 t, %1; cvt.u32.u64 %0, t; }" : "=r"(a) : "l"(p));
    return a;
}
__device__ __forceinline__ u32 pack_h2(float a, float b) {
    __half2 t = __floats2half2_rn(a, b);
    return *reinterpret_cast<u32*>(&t);
}
__device__ __forceinline__ void lds128(u32& r0, u32& r1, u32& r2, u32& r3, u32 addr) {
    asm volatile("ld.shared.v4.u32 {%0,%1,%2,%3}, [%4];"
                 : "=r"(r0), "=r"(r1), "=r"(r2), "=r"(r3) : "r"(addr));
}
__device__ __forceinline__ void mmaf16(float& c0, float& c1, float& c2, float& c3,
                                       u32 a0, u32 a1, u32 a2, u32 a3,
                                       u32 b0, u32 b1) {
    asm volatile("mma.sync.aligned.m16n8k16.row.col.f32.f16.f16.f32 "
                 "{%0,%1,%2,%3}, {%4,%5,%6,%7}, {%8,%9}, {%0,%1,%2,%3};"
                 : "+f"(c0), "+f"(c1), "+f"(c2), "+f"(c3)
                 : "r"(a0), "r"(a1), "r"(a2), "r"(a3), "r"(b0), "r"(b1));
}
__device__ __forceinline__ void cpasync16(u32 dst, const void* src) {
    asm volatile("cp.async.cg.shared.global [%0], [%1], 16;" :: "r"(dst), "l"(src));
}
#define CP_COMMIT() asm volatile("cp.async.commit_group;" ::: "memory")
#define CP_WAIT1()  asm volatile("cp.async.wait_group 1;" ::: "memory")

// ---- packed f32x2 ----
__device__ __forceinline__ u64 pk2(float lo, float hi) {
    u64 r; asm("mov.b64 %0, {%1, %2};" : "=l"(r) : "f"(lo), "f"(hi)); return r;
}
__device__ __forceinline__ void upk2(u64 v, float& lo, float& hi) {
    asm("mov.b64 {%0, %1}, %2;" : "=f"(lo), "=f"(hi) : "l"(v));
}
__device__ __forceinline__ u64 dup2(float x) {
    u64 r; asm("mov.b64 %0, {%1, %1};" : "=l"(r) : "f"(x)); return r;
}
__device__ __forceinline__ u64 fma2(u64 a, u64 b, u64 c) {
    u64 d; asm("fma.rn.f32x2 %0, %1, %2, %3;" : "=l"(d) : "l"(a), "l"(b), "l"(c)); return d;
}
__device__ __forceinline__ u64 mul2(u64 a, u64 b) {
    u64 d; asm("mul.rn.f32x2 %0, %1, %2;" : "=l"(d) : "l"(a), "l"(b)); return d;
}
__device__ __forceinline__ u64 add2(u64 a, u64 b) {
    u64 d; asm("add.rn.f32x2 %0, %1, %2;" : "=l"(d) : "l"(a), "l"(b)); return d;
}

__device__ __forceinline__ float ex2f(float x){ float r; asm("ex2.approx.ftz.f32 %0, %1;" : "=f"(r) : "f"(x)); return r; }
__device__ __forceinline__ float tanhf_fast(float x){ float r; asm("tanh.approx.f32 %0, %1;" : "=f"(r) : "f"(x)); return r; }
__device__ __forceinline__ float sigmoid_ht(float halfarg) {
    return fmaf(tanhf_fast(halfarg), 0.5f, 0.5f);
}
// softplus(x) = max(x,0) + ln(1+e), e = 2^(-|x|*log2e); ln(1+e) via deg-5 minimax
__device__ __forceinline__ float softplusf_fast(float x) {
    float e = ex2f(-1.4426950408889634f * fabsf(x));
    float p = fmaf(0.03215845f, e, -0.13606275f);
    p = fmaf(p, e, 0.28947478f);
    p = fmaf(p, e, -0.49190896f);
    p = fmaf(p, e, 0.99949556f);
    return fmaxf(x, 0.0f) + p * e;
}

// ---------------- prep: f32 W -> fp16 frag-major image ----------------
__global__ __launch_bounds__(256)
void prep_weights_kernel(const float* __restrict__ tnw)
{
    __shared__ float s[32][257];
    int bl = blockIdx.x;           // 0..127
    int l = bl & 1, b = bl >> 1;
    const float* wl = tnw + (size_t)b * TW + (l == 0 ? 2048 : 69120);
    int t = threadIdx.x;
    u32* gh = (u32*)g_wbf;

    for (int kc = 0; kc < 8; ++kc) {
        __syncthreads();
        #pragma unroll
        for (int j = 0; j < 32; ++j) {
            int idx = t + j * 256;               // 8192 floats
            int r = idx >> 8, c = idx & 255;
            s[r][c] = wl[(size_t)(kc * 32 + r) * 256 + c];
        }
        __syncthreads();
        size_t base0 = ((size_t)(b * 2 + l) * 8 + kc) * 4096;
        #pragma unroll
        for (int j = 0; j < 16; ++j) {
            int idx = t + j * 256;               // 0..4095
            int reg = idx & 3;
            int lid = (idx >> 2) & 31;
            int n16 = (idx >> 7) & 15;
            int ks  = idx >> 11;
            int koff = ks * 16 + 2 * (lid & 3) + 8 * (reg & 1);
            int n = n16 * 16 + (lid >> 2) + 8 * (reg >> 1);
            gh[base0 + idx] = pack_h2(s[koff][n], s[koff + 1][n]);
        }
    }
}

// ---------------- main kernel: 256 threads, 8 warps (64x32 warp tiles), 2 CTAs/SM ----------------
__global__ __launch_bounds__(256, 2)
void ode_hypernet_mma_kernel(const float* __restrict__ ctx_g,
                             const float* __restrict__ y_g,
                             const float* __restrict__ yp_g,
                             const float* __restrict__ tnw_g,
                             float* __restrict__ out_g)
{
    extern __shared__ char smc[];
    float* par = (float*)(smc + SM_PAR);
    const u32 smb = smem_u32(smc);

    const int tid = threadIdx.x;
    const int lid = tid & 31;
    const int wid = tid >> 5;        // = wn, 8 warps x 32 cols
    const int b  = blockIdx.y;
    const int p0 = blockIdx.x * TP;
    const float* w = tnw_g + (size_t)b * TW;
    const char* gw = (const char*)g_wbf;

    // per-warp B copy (each warp copies exactly the region it reads)
    auto load_chunk_g = [&](int g) {
        size_t src = ((size_t)(b * 2 + (g >> 3)) * 8 + (size_t)(g & 7)) * 16384;
        u32 dbase = smb + SM_B + (u32)(g % 3) * 16384;
        #pragma unroll
        for (int ks = 0; ks < 2; ++ks)
            #pragma unroll
            for (int nt = 0; nt < 2; ++nt) {
                u32 off = (u32)((ks * 16 + wid * 2 + nt) * 32 + lid) * 16;
                cpasync16(dbase + off, gw + src + off);
            }
        CP_COMMIT();
    };

    // ---- initial loads ----
    if (tid < 64) {
        size_t base = ((size_t)b * NN + p0 + tid) * 2;
        float4 rp = make_float4(ctx_g[(size_t)b * NN + p0 + tid],
                                yp_g[base + 0], yp_g[base + 1], 0.0f);
        *(float4*)&par[PF_ROWP + tid * 4] = rp;
    }
    if (tid < 128) par[PF_YS + tid] = y_g[((size_t)b * NN + p0) * 2 + tid];
    {
        // film0 [col][4] (wsc,bsc pre-halved) and W0I [col][4]
        float4 f0 = make_float4(w[1024 + tid], w[1280 + tid] * 0.5f,
                                w[1536 + tid] * 0.5f, w[1792 + tid]);
        float4 w0 = make_float4(w[tid], w[256 + tid], w[512 + tid], w[768 + tid]);
        *(float4*)&par[PF_FILMI + tid * 4] = f0;
        *(float4*)&par[PF_FILMI + 1024 + tid * 4] = w0;
    }
    if (tid < 16)
        par[PF_W3T + tid] = (tid < 4) ? w[136192 + 512 + tid]
                          : (tid < 12 ? w[136708 + tid - 4] : 0.0f);

    load_chunk_g(0);
    load_chunk_g(1);
    __syncthreads();

    // ---- layer 0 (SIMT): 4 -> 256, FiLM + softplus, write A fp16 frag-major ----
    {
        int p = tid & 63;
        int h2 = tid >> 6;           // 0..3, 64 channels each
        float4 rp = *(float4*)&par[PF_ROWP + p * 4];
        float cc = rp.x, q0 = rp.y, q1 = rp.z;
        float y0 = par[PF_YS + 2 * p], y1 = par[PF_YS + 2 * p + 1];
        int m16 = p >> 4;
        int plid4 = (p & 7) * 4;
        int preg = (p >> 3) & 1;
        #pragma unroll 4
        for (int j = 0; j < 32; ++j) {
            int ch = h2 * 64 + 2 * j;
            float4 wa = *(float4*)&par[PF_FILMI + 1024 + ch * 4];
            float4 wb = *(float4*)&par[PF_FILMI + 1024 + (ch + 1) * 4];
            float4 f0 = *(float4*)&par[PF_FILMI + ch * 4];
            float4 f1 = *(float4*)&par[PF_FILMI + (ch + 1) * 4];
            float v0 = y0 * wa.x + y1 * wa.y + q0 * wa.z + q1 * wa.w + f0.x;
            float v1 = y0 * wb.x + y1 * wb.y + q0 * wb.z + q1 * wb.w + f1.x;
            float s0 = sigmoid_ht(cc * f0.y + f0.z);
            float s1 = sigmoid_ht(cc * f1.y + f1.z);
            v0 = s0 * v0 + cc * f0.w;
            v1 = s1 * v1 + cc * f1.w;
            v0 = softplusf_fast(v0);
            v1 = softplusf_fast(v1);
            int k16 = ch >> 4;
            int flid = plid4 + (j & 3);
            int reg  = preg + 2 * ((j >> 2) & 1);
            u32 off = (u32)((m16 * 16 + k16) * 32 + flid) * 16 + (u32)reg * 4;
            *(u32*)(smc + SM_A + off) = pack_h2(v0, v1);
        }
    }
    __syncthreads();   // A ready; FILMI(l0) reads done before l1 overwrite

    u64 psp[8];                      // packed layer-3 partials (ps0, ps1) per (mi,rh)

    #pragma unroll 1
    for (int l = 1; l <= 2; ++l) {
        const float* wl = w + ((l == 1) ? 2048 : 69120);
        const float* fp = wl + 66048;
        if (tid < 128) {
            // pair-major FILMI [pair][16]
            int c0 = 2 * tid, c1 = c0 + 1;
            float4 pa = make_float4(fp[c0], fp[c1],
                                    fp[256 + c0] * 0.5f, fp[256 + c1] * 0.5f);
            float4 pb = make_float4(fp[512 + c0] * 0.5f, fp[512 + c1] * 0.5f,
                                    fp[768 + c0], fp[768 + c1]);
            float4 pc = make_float4(wl[65536 + c0], wl[65536 + c1],
                                    wl[65792 + c0], wl[65792 + c1]);
            float4 pd = make_float4(0.f, 0.f, 0.f, 0.f);
            if (l == 2) {
                pd.x = w[136192 + 2 * c0]; pd.y = w[136192 + 2 * c0 + 1];
                pd.z = w[136192 + 2 * c1]; pd.w = w[136192 + 2 * c1 + 1];
            }
            *(float4*)&par[PF_FILMI + tid * 16]      = pa;
            *(float4*)&par[PF_FILMI + tid * 16 + 4]  = pb;
            *(float4*)&par[PF_FILMI + tid * 16 + 8]  = pc;
            *(float4*)&par[PF_FILMI + tid * 16 + 12] = pd;
        }

        float acc[4][4][4];
        #pragma unroll
        for (int mi = 0; mi < 4; ++mi)
            #pragma unroll
            for (int n8 = 0; n8 < 4; ++n8)
                #pragma unroll
                for (int q = 0; q < 4; ++q) acc[mi][n8][q] = 0.0f;

        // barrier-free K-stream: each warp waits only on ITS OWN cp groups
        #pragma unroll 1
        for (int item = 0; item < 8; ++item) {
            int g = (l - 1) * 8 + item;
            CP_WAIT1();              // own group g complete (<=1 newer pending)
            if (g < 14) load_chunk_g(g + 2);

            u32 bbuf = smb + SM_B + (u32)(g % 3) * 16384;
            #pragma unroll
            for (int ks = 0; ks < 2; ++ks) {
                int k16 = item * 2 + ks;
                u32 a[4][4];
                #pragma unroll
                for (int mi = 0; mi < 4; ++mi)
                    lds128(a[mi][0], a[mi][1], a[mi][2], a[mi][3],
                           smb + SM_A + (u32)((mi * 16 + k16) * 32 + lid) * 16);
                u32 bh[2][4];
                #pragma unroll
                for (int nt = 0; nt < 2; ++nt) {
                    u32 off = (u32)((ks * 16 + wid * 2 + nt) * 32 + lid) * 16;
                    lds128(bh[nt][0], bh[nt][1], bh[nt][2], bh[nt][3], bbuf + off);
                }
                #pragma unroll
                for (int mi = 0; mi < 4; ++mi)
                    #pragma unroll
                    for (int n8 = 0; n8 < 4; ++n8) {
                        int nt = n8 >> 1, pp = (n8 & 1) * 2;
                        mmaf16(acc[mi][n8][0], acc[mi][n8][1], acc[mi][n8][2], acc[mi][n8][3],
                               a[mi][0], a[mi][1], a[mi][2], a[mi][3],
                               bh[nt][pp], bh[nt][pp + 1]);
                    }
            }
        }
        __syncthreads();   // all warps' reads of A done before epilogue overwrites A

        if (l == 2) {
            if (tid < 128) par[PF_RED + tid] = 0.0f;
            #pragma unroll
            for (int i = 0; i < 8; ++i) psp[i] = 0ull;
            __syncthreads();
        }

        // ---- epilogue: FiLM + softplus, f32x2-packed ----
        const u64 HALF2 = dup2(0.5f);
        const u64 C5 = dup2(0.03215845f), C4 = dup2(-0.13606275f);
        const u64 C3 = dup2(0.28947478f), C2 = dup2(-0.49190896f);
        const u64 C1 = dup2(0.99949556f);
        #pragma unroll
        for (int n8 = 0; n8 < 4; ++n8) {
            int pr = wid * 16 + n8 * 4 + (lid & 3);
            const float4* fbp = (const float4*)&par[PF_FILMI + pr * 16];
            float4 F0 = fbp[0], F1 = fbp[1], F2 = fbp[2], F3 = fbp[3];
            u64 bip  = pk2(F0.x, F0.y), wscp = pk2(F0.z, F0.w);
            u64 bscp = pk2(F1.x, F1.y), wshp = pk2(F1.z, F1.w);
            u64 wt0p = pk2(F2.x, F2.y), wt1p = pk2(F2.z, F2.w);
            u64 w3a  = pk2(F3.x, F3.y), w3b  = pk2(F3.z, F3.w);
            int k16n = wid * 2 + (n8 >> 1);     // next-layer k16 of this col pair
            #pragma unroll
            for (int mi = 0; mi < 4; ++mi) {
                #pragma unroll
                for (int rh = 0; rh < 2; ++rh) {
                    int row = mi * 16 + (lid >> 2) + rh * 8;
                    float4 rp = *(float4*)&par[PF_ROWP + row * 4];
                    u64 ccd = dup2(rp.x), q0d = dup2(rp.y), q1d = dup2(rp.z);
                    u64 vv = pk2(acc[mi][n8][rh * 2 + 0], acc[mi][n8][rh * 2 + 1]);
                    vv = add2(vv, bip);
                    vv = fma2(q0d, wt0p, vv);
                    vv = fma2(q1d, wt1p, vv);
                    u64 sarg = fma2(ccd, wscp, bscp);
                    float sa0, sa1; upk2(sarg, sa0, sa1);
                    u64 tp = pk2(tanhf_fast(sa0), tanhf_fast(sa1));
                    u64 sig = fma2(tp, HALF2, HALF2);
                    u64 cw = mul2(ccd, wshp);
                    vv = fma2(sig, vv, cw);
                    // packed softplus
                    float x0, x1; upk2(vv, x0, x1);
                    float e0 = ex2f(-1.4426950408889634f * fabsf(x0));
                    float e1 = ex2f(-1.4426950408889634f * fabsf(x1));
                    u64 ep = pk2(e0, e1);
                    u64 pp2 = fma2(C5, ep, C4);
                    pp2 = fma2(pp2, ep, C3);
                    pp2 = fma2(pp2, ep, C2);
                    pp2 = fma2(pp2, ep, C1);
                    u64 pe = mul2(pp2, ep);
                    float g0, g1; upk2(pe, g0, g1);
                    float v0 = fmaxf(x0, 0.0f) + g0;
                    float v1 = fmaxf(x1, 0.0f) + g1;
                    if (l == 1) {
                        u32 off = (u32)((mi * 16 + k16n) * 32 + lid) * 16
                                + (u32)(rh + 2 * (n8 & 1)) * 4;
                        *(u32*)(smc + SM_A + off) = pack_h2(v0, v1);
                    } else {
                        psp[mi * 2 + rh] = fma2(dup2(v0), w3a, psp[mi * 2 + rh]);
                        psp[mi * 2 + rh] = fma2(dup2(v1), w3b, psp[mi * 2 + rh]);
                    }
                }
            }
        }
        __syncthreads();
    }

    // ---- layer-3 reduction: packed shuffle over 4 lanes sharing a row, then atomics ----
    #pragma unroll
    for (int mi = 0; mi < 4; ++mi)
        #pragma unroll
        for (int rh = 0; rh < 2; ++rh) {
            u64 pv = psp[mi * 2 + rh];
            pv = add2(pv, __shfl_xor_sync(0xffffffffu, pv, 1));
            pv = add2(pv, __shfl_xor_sync(0xffffffffu, pv, 2));
            if ((lid & 3) == 0) {
                float s0, s1; upk2(pv, s0, s1);
                int p = mi * 16 + (lid >> 2) + rh * 8;
                atomicAdd(&par[PF_RED + p * 2 + 0], s0);
                atomicAdd(&par[PF_RED + p * 2 + 1], s1);
            }
        }
    __syncthreads();

    if (tid < 128) {
        int p = tid >> 1;
        int o = tid & 1;
        float4 rp = *(float4*)&par[PF_ROWP + p * 4];
        float s = par[PF_RED + p * 2 + o];
        s += rp.y * par[PF_W3T + o] + rp.z * par[PF_W3T + 2 + o];
        float v = s + par[PF_W3T + 4 + o];
        float g = sigmoid_ht(0.5f * (rp.x * par[PF_W3T + 6 + o] + par[PF_W3T + 8 + o]));
        v = g * v + rp.x * par[PF_W3T + 10 + o];
        out_g[((size_t)b * NN + p0 + p) * 2 + o] = v;
    }
}

extern "C" void kernel_launch(void* const* d_in, const int* in_sizes, int n_in,
                              void* d_out, int out_size) {
    (void)in_sizes; (void)n_in; (void)out_size;
    const float* ctx = (const float*)d_in[0];
    const float* y   = (const float*)d_in[1];
    const float* yp  = (const float*)d_in[2];
    const float* tnw = (const float*)d_in[3];
    float* out = (float*)d_out;

    prep_weights_kernel<<<128, 256>>>(tnw);

    cudaFuncSetAttribute(ode_hypernet_mma_kernel,
                         cudaFuncAttributeMaxDynamicSharedMemorySize, SMEM_TOTAL);
    dim3 grid(NN / TP, BB);   // (32, 64)
    ode_hypernet_mma_kernel<<<grid, 256, SMEM_TOTAL>>>(ctx, y, yp, tnw, out);
}